// round 7
// baseline (speedup 1.0000x reference)
#include <cuda_runtime.h>
#include <math.h>

#define HH 192
#define WW 192
#define HW (192*192)

typedef unsigned long long u64;

// ---- packed fp32x2 helpers ----
__device__ __forceinline__ u64 pack2(float a, float b) {
    u64 r; asm("mov.b64 %0, {%1, %2};" : "=l"(r) : "f"(a), "f"(b)); return r;
}
__device__ __forceinline__ float2 unpack2(u64 v) {
    float2 f; asm("mov.b64 {%0, %1}, %2;" : "=f"(f.x), "=f"(f.y) : "l"(v)); return f;
}
__device__ __forceinline__ u64 fma2(u64 a, u64 b, u64 c) {
    u64 d; asm("fma.rn.f32x2 %0, %1, %2, %3;" : "=l"(d) : "l"(a), "l"(b), "l"(c)); return d;
}
__device__ __forceinline__ u64 mul2(u64 a, u64 b) {
    u64 d; asm("mul.rn.f32x2 %0, %1, %2;" : "=l"(d) : "l"(a), "l"(b)); return d;
}
// ---- fast transcendentals (HW MUFU paths) ----
__device__ __forceinline__ float tanh_fast(float x) {
    float y; asm("tanh.approx.f32 %0, %1;" : "=f"(y) : "f"(x)); return y;
}
__device__ __forceinline__ float sigmoid_fast(float x) {
    float e; asm("ex2.approx.f32 %0, %1;" : "=f"(e) : "f"(-x * 1.4426950408889634f));
    return __frcp_rn(1.f + e);
}

// ---- cp.async helpers ----
__device__ __forceinline__ void cp4(unsigned daddr, const float* src, bool valid) {
    asm volatile("cp.async.ca.shared.global [%0], [%1], 4, %2;"
                 :: "r"(daddr), "l"(src), "r"(valid ? 4u : 0u));
}
__device__ __forceinline__ void cp16(unsigned daddr, const void* src) {
    asm volatile("cp.async.cg.shared.global [%0], [%1], 16;" :: "r"(daddr), "l"(src));
}
__device__ __forceinline__ void cp_commit() {
    asm volatile("cp.async.commit_group;");
}
template<int N> __device__ __forceinline__ void cp_wait() {
    asm volatile("cp.async.wait_group %0;" :: "n"(N));
}

// ---- scratch ----
__device__ float g_h1[64 * HW];
__device__ float g_h2[64 * HW];
__device__ float g_out4[432 * HW];
__device__ float g_xT[HW * 128];
__device__ u64 g_pw1[8  * 192 * 36];
__device__ u64 g_pw2[8  *  64 * 36];
__device__ u64 g_pw3[8  *  64 * 36];
__device__ u64 g_pw4[54 *  64 * 36];
__device__ u64 g_pwd[32 * 1152];       // deform weights (w[o], w[o+32])

// ============================================================================
// Weight prepacks
// ============================================================================
__global__ void prepack_kernel(const float* __restrict__ wt, int CIN, int nOcg,
                               u64* __restrict__ dst)
{
    int i = blockIdx.x * 256 + threadIdx.x;
    int total = nOcg * CIN * 36;
    if (i >= total) return;
    int kk = i % 9; int t = i / 9;
    int pr = t % 4; t /= 4;
    int ci = t % CIN; int ocg = t / CIN;
    float wa = wt[((ocg * 8 + pr)     * CIN + ci) * 9 + kk];
    float wb = wt[((ocg * 8 + pr + 4) * CIN + ci) * 9 + kk];
    dst[i] = pack2(wa, wb);
}

__global__ void prepack_deform_kernel(const float* __restrict__ wt,
                                      u64* __restrict__ dst)
{
    int i = blockIdx.x * 256 + threadIdx.x;
    if (i >= 32 * 1152) return;
    int o = i / 1152, j = i - o * 1152;
    dst[i] = pack2(wt[o * 1152 + j], wt[(o + 32) * 1152 + j]);
}

// ============================================================================
// Direct 3x3 conv, FFMA2 oc-pair packing + cp.async double-buffered pipeline.
// ============================================================================
#define SIN_ELEMS (8*18*68)
#define SMEM_W_OFF (2*SIN_ELEMS*4)

template<int CIN, bool RELU>
__global__ void __launch_bounds__(256, 2) conv3x3_kernel(
    const float* __restrict__ in,
    const u64*   __restrict__ pw,
    const float* __restrict__ bs,
    float* __restrict__ out)
{
    extern __shared__ char dsm[];
    float* s_in = (float*)dsm;
    u64*   s_w  = (u64*)(dsm + SMEM_W_OFF);

    const int tid  = threadIdx.x;
    const int tx   = tid & 15;
    const int ty   = tid >> 4;
    const int lane = tid & 31;
    const int wid  = tid >> 5;
    const int bw   = blockIdx.x * 64;
    const int bh   = blockIdx.y * 16;
    const int bz   = blockIdx.z;
    const int ocg0 = bz * 8;
    const int NC   = CIN / 8;

    unsigned sin_addr = (unsigned)__cvta_generic_to_shared(s_in);
    unsigned sw_addr  = (unsigned)__cvta_generic_to_shared(s_w);

    auto prefetch = [&](int chunk, int buf) {
        int ci0 = chunk * 8;
        unsigned dbase = sin_addr + buf * (SIN_ELEMS * 4);
        const float* ibase = in + (size_t)ci0 * HW;
        for (int row = wid; row < 144; row += 8) {
            int cc = row / 18;
            int r  = row - cc * 18;
            int gy = bh - 1 + r;
            bool yok = (unsigned)gy < (unsigned)HH;
            int gyc = min(max(gy, 0), HH - 1);
            const float* src = ibase + (size_t)cc * HW + gyc * WW;
            unsigned drow = dbase + ((cc * 18 + r) * 68) * 4;
            #pragma unroll
            for (int s = 0; s < 3; s++) {
                int c0 = lane + s * 32;
                if (c0 < 66) {
                    int gx = bw - 1 + c0;
                    bool ok = yok && (unsigned)gx < (unsigned)WW;
                    int gxc = min(max(gx, 0), WW - 1);
                    cp4(drow + c0 * 4, src + gxc, ok);
                }
            }
        }
        const u64* wsrc = pw + (size_t)(bz * CIN + ci0) * 36;
        unsigned wdst = sw_addr + buf * (288 * 8);
        if (tid < 144) cp16(wdst + tid * 16, wsrc + tid * 2);
    };

    u64 acc[4][4];
    #pragma unroll
    for (int p = 0; p < 4; p++)
        #pragma unroll
        for (int q = 0; q < 4; q++) acc[p][q] = 0ull;

    prefetch(0, 0);
    cp_commit();

    for (int c = 0; c < NC; c++) {
        if (c + 1 < NC) {
            prefetch(c + 1, (c + 1) & 1);
            cp_commit();
            cp_wait<1>();
        } else {
            cp_wait<0>();
        }
        __syncthreads();

        const int buf = c & 1;
        const float* sin = s_in + buf * SIN_ELEMS;
        const u64*   sw  = s_w  + buf * 288;

        #pragma unroll
        for (int cc = 0; cc < 8; cc++) {
            #pragma unroll
            for (int kh = 0; kh < 3; kh++) {
                const float* rp = sin + ((cc * 18) + ty + kh) * 68 + tx * 4;
                float4 a = *(const float4*)rp;
                float2 b = *(const float2*)(rp + 4);
                u64 d[6];
                d[0] = pack2(a.x, a.x);
                d[1] = pack2(a.y, a.y);
                d[2] = pack2(a.z, a.z);
                d[3] = pack2(a.w, a.w);
                d[4] = pack2(b.x, b.x);
                d[5] = pack2(b.y, b.y);
                #pragma unroll
                for (int pr = 0; pr < 4; pr++) {
                    u64 w0 = sw[(cc * 4 + pr) * 9 + kh * 3 + 0];
                    u64 w1 = sw[(cc * 4 + pr) * 9 + kh * 3 + 1];
                    u64 w2 = sw[(cc * 4 + pr) * 9 + kh * 3 + 2];
                    #pragma unroll
                    for (int px = 0; px < 4; px++) {
                        acc[pr][px] = fma2(w0, d[px],     acc[pr][px]);
                        acc[pr][px] = fma2(w1, d[px + 1], acc[pr][px]);
                        acc[pr][px] = fma2(w2, d[px + 2], acc[pr][px]);
                    }
                }
            }
        }
        __syncthreads();
    }

    const size_t obase = (size_t)(bh + ty) * WW + bw + tx * 4;
    #pragma unroll
    for (int pr = 0; pr < 4; pr++) {
        float bva = bs[ocg0 + pr];
        float bvb = bs[ocg0 + pr + 4];
        float ra[4], rb[4];
        #pragma unroll
        for (int px = 0; px < 4; px++) {
            float2 f = unpack2(acc[pr][px]);
            float va = f.x + bva;
            float vb = f.y + bvb;
            if (RELU) {
                va = (va >= 0.f) ? va : 0.1f * va;
                vb = (vb >= 0.f) ? vb : 0.1f * vb;
            }
            ra[px] = va; rb[px] = vb;
        }
        *(float4*)&out[(size_t)(ocg0 + pr)     * HW + obase] =
            make_float4(ra[0], ra[1], ra[2], ra[3]);
        *(float4*)&out[(size_t)(ocg0 + pr + 4) * HW + obase] =
            make_float4(rb[0], rb[1], rb[2], rb[3]);
    }
}

#define CONV_SMEM (2*SIN_ELEMS*4 + 2*288*8)

// ============================================================================
// Transpose x: [128][HW] -> [HW][128].
// ============================================================================
__global__ void __launch_bounds__(256) transpose_kernel(
    const float* __restrict__ x, float* __restrict__ xT)
{
    __shared__ float s[32][33];
    int p0 = blockIdx.x * 32;
    int c0 = blockIdx.y * 32;
    int tx = threadIdx.x & 31;
    int ty = threadIdx.x >> 5;
    #pragma unroll
    for (int i = 0; i < 32; i += 8)
        s[ty + i][tx] = x[(size_t)(c0 + ty + i) * HW + p0 + tx];
    __syncthreads();
    #pragma unroll
    for (int i = 0; i < 32; i += 8)
        xT[(size_t)(p0 + ty + i) * 128 + c0 + tx] = s[tx][ty + i];
}

// ============================================================================
// Fused deformable conv. Packed-pair weights (u64), HW tanh/sigmoid.
// ============================================================================
#define DPX 32
__global__ void __launch_bounds__(256) deform_kernel(
    const float* __restrict__ xT,    // [HW][128]
    const float* __restrict__ out4,  // [432][HW]
    const u64*   __restrict__ pwd,   // [32][1152] pairs (w[o], w[o+32])
    const float* __restrict__ bs,
    float* __restrict__ out)
{
    __shared__ float val_s[72 * DPX];
    __shared__ u64   w2_s[32 * 73];

    const int tid = threadIdx.x;
    const int pbase = blockIdx.x * DPX;
    const int o  = tid & 31;
    const int ps = tid >> 5;

    u64 acc[2][2];
    acc[0][0] = acc[0][1] = acc[1][0] = acc[1][1] = 0ull;

    for (int g = 0; g < 16; g++) {
        __syncthreads();
        // stage packed weight pairs: 32 oc-pairs x 72
        for (int li = tid; li < 2304; li += 256) {
            int oo = li / 72;
            int j  = li - oo * 72;
            w2_s[oo * 73 + j] = pwd[oo * 1152 + g * 72 + j];
        }
        // build val tile: 9 taps x 32 px
        for (int t = tid; t < 9 * DPX; t += 256) {
            int pix = t & (DPX - 1);
            int k   = t >> 5;
            int p   = pbase + pix;
            int ho  = p / WW;
            int wo  = p - ho * WW;

            float offy = 5.f * tanh_fast(out4[(g * 18 + k * 2)     * HW + p]);
            float offx = 5.f * tanh_fast(out4[(g * 18 + k * 2 + 1) * HW + p]);
            float mv   = sigmoid_fast(out4[(288 + g * 9 + k) * HW + p]);

            float py = (float)(ho - 1 + k / 3) + offy;
            float px = (float)(wo - 1 + k % 3) + offx;
            float y0 = floorf(py), x0 = floorf(px);
            float wy1 = py - y0, wx1 = px - x0;

            u64 v2[4] = {0ull, 0ull, 0ull, 0ull};

            auto corner = [&](float yf, float xf, float wc) {
                if (yf >= 0.f && yf <= (float)(HH - 1) &&
                    xf >= 0.f && xf <= (float)(WW - 1)) {
                    int iy = (int)yf, ix = (int)xf;
                    const ulonglong2* q =
                        (const ulonglong2*)(xT + ((size_t)(iy * WW + ix) << 7) + (g << 3));
                    ulonglong2 q0 = q[0], q1 = q[1];
                    u64 wc2 = pack2(wc, wc);
                    v2[0] = fma2(wc2, q0.x, v2[0]);
                    v2[1] = fma2(wc2, q0.y, v2[1]);
                    v2[2] = fma2(wc2, q1.x, v2[2]);
                    v2[3] = fma2(wc2, q1.y, v2[3]);
                }
            };
            corner(y0,       x0,       (1.f - wy1) * (1.f - wx1));
            corner(y0,       x0 + 1.f, (1.f - wy1) * wx1);
            corner(y0 + 1.f, x0,       wy1 * (1.f - wx1));
            corner(y0 + 1.f, x0 + 1.f, wy1 * wx1);

            u64 m2 = pack2(mv, mv);
            #pragma unroll
            for (int c2 = 0; c2 < 4; c2++) {
                float2 ff = unpack2(mul2(v2[c2], m2));
                val_s[((c2 * 2)     * 9 + k) * DPX + pix] = ff.x;
                val_s[((c2 * 2 + 1) * 9 + k) * DPX + pix] = ff.y;
            }
        }
        __syncthreads();

        // GEMM: acc[pair][px] += (w[o],w[o+32])[j] * val[j][px]
        const u64*   wr = &w2_s[o * 73];
        const float* vb = &val_s[ps * 4];
        #pragma unroll 4
        for (int j = 0; j < 72; j++) {
            u64 wp = wr[j];                    // (w[o], w[o+32])
            const u64* vp = (const u64*)(vb + j * DPX);
            u64 v0 = vp[0], v1 = vp[1];
            float2 wf = unpack2(wp);
            u64 w02 = pack2(wf.x, wf.x);
            u64 w12 = pack2(wf.y, wf.y);
            acc[0][0] = fma2(w02, v0, acc[0][0]);
            acc[0][1] = fma2(w02, v1, acc[0][1]);
            acc[1][0] = fma2(w12, v0, acc[1][0]);
            acc[1][1] = fma2(w12, v1, acc[1][1]);
        }
    }

    float bv0 = bs[o], bv1 = bs[o + 32];
    float2 a0 = unpack2(acc[0][0]), a1 = unpack2(acc[0][1]);
    float2 b0 = unpack2(acc[1][0]), b1 = unpack2(acc[1][1]);
    *(float4*)&out[(size_t)o        * HW + pbase + ps * 4] =
        make_float4(a0.x + bv0, a0.y + bv0, a1.x + bv0, a1.y + bv0);
    *(float4*)&out[(size_t)(o + 32) * HW + pbase + ps * 4] =
        make_float4(b0.x + bv1, b0.y + bv1, b1.x + bv1, b1.y + bv1);
}

// ============================================================================
// launch
// ============================================================================
extern "C" void kernel_launch(void* const* d_in, const int* in_sizes, int n_in,
                              void* d_out, int out_size)
{
    const float* x      = (const float*)d_in[0];
    const float* cond   = (const float*)d_in[1];
    const float* weight = (const float*)d_in[2];
    const float* bias   = (const float*)d_in[3];
    const float* w1     = (const float*)d_in[4];
    const float* b1     = (const float*)d_in[5];
    const float* w2     = (const float*)d_in[6];
    const float* b2     = (const float*)d_in[7];
    const float* w3     = (const float*)d_in[8];
    const float* b3     = (const float*)d_in[9];
    const float* w4     = (const float*)d_in[10];
    const float* b4     = (const float*)d_in[11];
    float* out = (float*)d_out;

    float *h1, *h2, *o4, *xT;
    u64 *pw1, *pw2, *pw3, *pw4, *pwd;
    cudaGetSymbolAddress((void**)&h1, g_h1);
    cudaGetSymbolAddress((void**)&h2, g_h2);
    cudaGetSymbolAddress((void**)&o4, g_out4);
    cudaGetSymbolAddress((void**)&xT, g_xT);
    cudaGetSymbolAddress((void**)&pw1, g_pw1);
    cudaGetSymbolAddress((void**)&pw2, g_pw2);
    cudaGetSymbolAddress((void**)&pw3, g_pw3);
    cudaGetSymbolAddress((void**)&pw4, g_pw4);
    cudaGetSymbolAddress((void**)&pwd, g_pwd);

    prepack_kernel<<<(8  * 192 * 36 + 255) / 256, 256>>>(w1, 192, 8,  pw1);
    prepack_kernel<<<(8  *  64 * 36 + 255) / 256, 256>>>(w2,  64, 8,  pw2);
    prepack_kernel<<<(8  *  64 * 36 + 255) / 256, 256>>>(w3,  64, 8,  pw3);
    prepack_kernel<<<(54 *  64 * 36 + 255) / 256, 256>>>(w4,  64, 54, pw4);
    prepack_deform_kernel<<<(32 * 1152 + 255) / 256, 256>>>(weight, pwd);

    cudaFuncSetAttribute(conv3x3_kernel<192, true>,
                         cudaFuncAttributeMaxDynamicSharedMemorySize, CONV_SMEM);
    cudaFuncSetAttribute(conv3x3_kernel<64, true>,
                         cudaFuncAttributeMaxDynamicSharedMemorySize, CONV_SMEM);
    cudaFuncSetAttribute(conv3x3_kernel<64, false>,
                         cudaFuncAttributeMaxDynamicSharedMemorySize, CONV_SMEM);

    dim3 cgrid(3, 12, 8);
    conv3x3_kernel<192, true ><<<cgrid, 256, CONV_SMEM>>>(cond, pw1, b1, h1);
    conv3x3_kernel< 64, true ><<<cgrid, 256, CONV_SMEM>>>(h1,   pw2, b2, h2);
    conv3x3_kernel< 64, true ><<<cgrid, 256, CONV_SMEM>>>(h2,   pw3, b3, h1);
    dim3 cgrid4(3, 12, 54);
    conv3x3_kernel< 64, false><<<cgrid4, 256, CONV_SMEM>>>(h1,  pw4, b4, o4);

    transpose_kernel<<<dim3(1152, 4), 256>>>(x, xT);

    deform_kernel<<<HW / DPX, 256>>>(xT, o4, pwd, bias, out);
}